// round 5
// baseline (speedup 1.0000x reference)
#include <cuda_runtime.h>
#include <cuda_bf16.h>
#include <math.h>
#include <stdint.h>

// ---------------------------------------------------------------------------
// SwinBlock. tf32 tensor-core GEMMs with ldmatrix fragment loads (B weights
// pre-transposed to [N][K] tf32), 3-stage cp.async; tf32 mma attention.
// ---------------------------------------------------------------------------

#define TOK     100352
#define CDIM    192
#define HIDDEN  768
#define QKVDIM  576
#define NWIN    2048
#define NHEAD   6
#define HD      32
#define WN      49

__device__ float g_xn  [ (size_t)TOK * CDIM   ];
__device__ float g_qkv [ (size_t)TOK * HIDDEN ];
__device__ float g_attn[ (size_t)TOK * CDIM   ];
__device__ float g_xa  [ (size_t)TOK * CDIM   ];
// tf32-rounded, TRANSPOSED weights: [N][K]
__device__ float g_wq [ QKVDIM * CDIM ];
__device__ float g_wp [ CDIM * CDIM   ];
__device__ float g_w1 [ HIDDEN * CDIM ];
__device__ float g_w2 [ CDIM * HIDDEN ];

#define F2TF(u, f) \
    asm volatile("cvt.rna.tf32.f32 %0, %1;" : "=r"(u) : "f"(f))

__device__ __forceinline__ float round_tf32(float f) {
    uint32_t u; F2TF(u, f); return __uint_as_float(u);
}

__device__ __forceinline__ int nat_index(int r) {
    int widx = r / WN, n = r % WN;
    int b  = widx >> 6, wi = widx & 63;
    int hs = (wi >> 3) * 7 + n / 7;
    int ws = (wi & 7)  * 7 + n % 7;
    int h = hs + 3; if (h >= 56) h -= 56;
    int w = ws + 3; if (w >= 56) w -= 56;
    return b * 3136 + h * 56 + w;
}

#define MMA_TF32(c, a, b) \
    asm volatile("mma.sync.aligned.m16n8k8.row.col.f32.tf32.tf32.f32 " \
        "{%0,%1,%2,%3},{%4,%5,%6,%7},{%8,%9},{%0,%1,%2,%3};" \
        : "+f"(c[0]), "+f"(c[1]), "+f"(c[2]), "+f"(c[3]) \
        : "r"(a[0]), "r"(a[1]), "r"(a[2]), "r"(a[3]), "r"(b[0]), "r"(b[1]))

#define LDSM4(r0, r1, r2, r3, addr) \
    asm volatile("ldmatrix.sync.aligned.m8n8.x4.shared.b16 {%0,%1,%2,%3}, [%4];" \
        : "=r"(r0), "=r"(r1), "=r"(r2), "=r"(r3) : "r"(addr))

#define CPA16(dst, src) \
    asm volatile("cp.async.cg.shared.global [%0], [%1], 16;" :: "r"(dst), "l"(src))

// ---------------------------------------------------------------------------
// Weight preprocessing: tf32-round AND transpose [K][N] -> [N][K]
// ---------------------------------------------------------------------------
__global__ void wconv_kernel(const float* __restrict__ a, float* __restrict__ oa, int ka, int na,
                             const float* __restrict__ b, float* __restrict__ ob, int kb, int nb,
                             const float* __restrict__ c, float* __restrict__ oc, int kc, int nc,
                             const float* __restrict__ d, float* __restrict__ od, int kd, int nd)
{
    int i = blockIdx.x * blockDim.x + threadIdx.x;
    int stride = gridDim.x * blockDim.x;
    for (int t = i; t < ka * na; t += stride) {
        int k = t / na, n = t % na;
        oa[n * ka + k] = round_tf32(a[t]);
    }
    for (int t = i; t < kb * nb; t += stride) {
        int k = t / nb, n = t % nb;
        ob[n * kb + k] = round_tf32(b[t]);
    }
    for (int t = i; t < kc * nc; t += stride) {
        int k = t / nc, n = t % nc;
        oc[n * kc + k] = round_tf32(c[t]);
    }
    for (int t = i; t < kd * nd; t += stride) {
        int k = t / nd, n = t % nd;
        od[n * kd + k] = round_tf32(d[t]);
    }
}

// ---------------------------------------------------------------------------
// LayerNorm: one warp per token; output rounded to tf32
// ---------------------------------------------------------------------------
__global__ __launch_bounds__(256) void ln_kernel(
    const float* __restrict__ x, const float* __restrict__ g,
    const float* __restrict__ be, float* __restrict__ out, int gather)
{
    int r = (blockIdx.x * blockDim.x + threadIdx.x) >> 5;
    if (r >= TOK) return;
    int lane = threadIdx.x & 31;
    int src = gather ? nat_index(r) : r;
    const float* p = x + (size_t)src * CDIM;
    float v[6]; float s = 0.f, sq = 0.f;
#pragma unroll
    for (int i = 0; i < 6; i++) {
        v[i] = p[lane + 32 * i];
        s += v[i]; sq += v[i] * v[i];
    }
#pragma unroll
    for (int o = 16; o > 0; o >>= 1) {
        s  += __shfl_xor_sync(0xffffffffu, s,  o);
        sq += __shfl_xor_sync(0xffffffffu, sq, o);
    }
    float mean = s * (1.f / CDIM);
    float var  = sq * (1.f / CDIM) - mean * mean;
    float rstd = rsqrtf(var + 1e-5f);
    float* q = out + (size_t)r * CDIM;
#pragma unroll
    for (int i = 0; i < 6; i++) {
        int c = lane + 32 * i;
        q[c] = round_tf32((v[i] - mean) * rstd * g[c] + be[c]);
    }
}

// ---------------------------------------------------------------------------
// tf32 GEMM:  C[M,N] = A[M,K] @ Bt[N,K]^T  (+epilogues)
// Tile 128x64x16, 256 thr, 8 warps (4M x 2N), warp tile 32x32.
// Fragment loads via ldmatrix.x4 on fp32 data (b16 LDSM trick).
// ---------------------------------------------------------------------------
#define AP  20    // As pitch (floats), odd 16B units -> conflict-free LDSM
#define BPK 20    // Bs pitch (floats), [n][k] layout
#define STG 3

enum { EPI_BIAS = 0, EPI_PROJ = 1, EPI_GELU = 2, EPI_RES = 3 };

__device__ __forceinline__ float gelu_exact(float v) {
    return 0.5f * v * (1.0f + erff(v * 0.70710678118654752f));
}

template<int EPI>
__global__ __launch_bounds__(256) void gemm_tc(
    const float* __restrict__ A, const float* __restrict__ Bt,
    const float* __restrict__ bias, float* __restrict__ C,
    const float* __restrict__ res, int M, int N, int K)
{
    __shared__ float As[STG][128 * AP];
    __shared__ float Bs[STG][64 * BPK];

    const int tid  = threadIdx.x;
    const int lane = tid & 31, warp = tid >> 5;
    const int wm = (warp & 3) * 32;
    const int wn = (warp >> 2) * 32;
    const int m0 = blockIdx.y * 128, n0 = blockIdx.x * 64;

    // cp.async loader mapping
    const int ar  = tid >> 2;             // A row 0..63 (and +64)
    const int ac  = (tid & 3) * 4;        // A k-chunk
    const int br  = tid >> 2;             // B n-row 0..63
    const int bkc = (tid & 3) * 4;        // B k-chunk

    const float* Ag0 = A + (size_t)(m0 + ar) * K + ac;
    const float* Ag1 = Ag0 + (size_t)64 * K;
    const float* Bg  = Bt + (size_t)(n0 + br) * K + bkc;

    const uint32_t sa0 = (uint32_t)__cvta_generic_to_shared(&As[0][ar * AP + ac]);
    const uint32_t sa1 = (uint32_t)__cvta_generic_to_shared(&As[0][(ar + 64) * AP + ac]);
    const uint32_t sb  = (uint32_t)__cvta_generic_to_shared(&Bs[0][br * BPK + bkc]);
    const uint32_t ASTB = sizeof(float) * 128 * AP;   // 10240
    const uint32_t BSTB = sizeof(float) * 64 * BPK;   // 5120

    // ldmatrix source addresses (per-lane, buffer 0, ks=0)
    const int a_row = wm + ((lane >> 3) & 1) * 8 + (lane & 7);
    const int a_col = (lane >> 4) * 4;
    const uint32_t aAddr = (uint32_t)__cvta_generic_to_shared(&As[0][a_row * AP + a_col]);
    const int b_n = wn + ((lane >> 4) & 1) * 8 + (lane & 7);
    const int b_k = ((lane >> 3) & 1) * 4;
    const uint32_t bAddr = (uint32_t)__cvta_generic_to_shared(&Bs[0][b_n * BPK + b_k]);

    float acc[2][4][4];
#pragma unroll
    for (int mi = 0; mi < 2; mi++)
#pragma unroll
        for (int ni = 0; ni < 4; ni++)
#pragma unroll
            for (int j = 0; j < 4; j++) acc[mi][ni][j] = 0.f;

    const int KT = K >> 4;

#pragma unroll
    for (int s = 0; s < STG - 1; s++) {
        CPA16(sa0 + s * ASTB, Ag0 + s * 16);
        CPA16(sa1 + s * ASTB, Ag1 + s * 16);
        CPA16(sb  + s * BSTB, Bg + s * 16);
        asm volatile("cp.async.commit_group;");
    }

    for (int kt = 0; kt < KT; kt++) {
        if (kt + 2 < KT) {
            const int nb = (kt + 2) % STG;
            CPA16(sa0 + nb * ASTB, Ag0 + (kt + 2) * 16);
            CPA16(sa1 + nb * ASTB, Ag1 + (kt + 2) * 16);
            CPA16(sb  + nb * BSTB, Bg + (kt + 2) * 16);
        }
        asm volatile("cp.async.commit_group;");
        asm volatile("cp.async.wait_group 2;");
        __syncthreads();

        const uint32_t aoff = (kt % STG) * ASTB;
        const uint32_t boff = (kt % STG) * BSTB;
#pragma unroll
        for (int ks = 0; ks < 2; ks++) {
            uint32_t af[2][4], bf[4][2];
            LDSM4(af[0][0], af[0][1], af[0][2], af[0][3], aAddr + aoff + ks * 32);
            LDSM4(af[1][0], af[1][1], af[1][2], af[1][3],
                  aAddr + aoff + 16 * AP * 4 + ks * 32);
            LDSM4(bf[0][0], bf[0][1], bf[1][0], bf[1][1], bAddr + boff + ks * 32);
            LDSM4(bf[2][0], bf[2][1], bf[3][0], bf[3][1],
                  bAddr + boff + 16 * BPK * 4 + ks * 32);
#pragma unroll
            for (int mi = 0; mi < 2; mi++)
#pragma unroll
                for (int ni = 0; ni < 4; ni++)
                    MMA_TF32(acc[mi][ni], af[mi], bf[ni]);
        }
        __syncthreads();
    }

    // epilogue
#pragma unroll
    for (int mi = 0; mi < 2; mi++) {
#pragma unroll
        for (int h = 0; h < 2; h++) {
            const int row = m0 + wm + mi * 16 + (lane >> 2) + h * 8;
            size_t orow;
            if (EPI == EPI_PROJ) orow = (size_t)nat_index(row) * N;
            else                 orow = (size_t)row * N;
#pragma unroll
            for (int ni = 0; ni < 4; ni++) {
                const int cc = n0 + wn + ni * 8 + (lane & 3) * 2;
                float v0 = acc[mi][ni][2 * h + 0] + bias[cc];
                float v1 = acc[mi][ni][2 * h + 1] + bias[cc + 1];
                if (EPI == EPI_GELU) {
                    v0 = round_tf32(gelu_exact(v0));
                    v1 = round_tf32(gelu_exact(v1));
                }
                if (EPI == EPI_RES) {
                    v0 += res[(size_t)row * N + cc];
                    v1 += res[(size_t)row * N + cc + 1];
                }
                *(float2*)(C + orow + cc) = make_float2(v0, v1);
            }
        }
    }
}

// ---------------------------------------------------------------------------
// Attention on tensor cores (as round 4; P stored tf32-rounded).
// ---------------------------------------------------------------------------
#define ATQ 36
#define ATK 72
#define ATS 60
#define ATV 40

__global__ __launch_bounds__(128) void attn_mma_kernel(
    const float* __restrict__ qkv, float* __restrict__ out)
{
    const int widx = blockIdx.x;
    const int head = blockIdx.y;
    __shared__ float Q [64 * ATQ];
    __shared__ float Kt[32 * ATK];
    __shared__ float S [64 * ATS];
    __shared__ float V [56 * ATV];

    const int tid = threadIdx.x;
    const int lane = tid & 31, warp = tid >> 5;
    const int wm = warp * 16;

    // zero pads: V rows 49..55, Q rows 49..63
    for (int t = tid; t < 7 * ATV; t += 128) V[49 * ATV + t] = 0.f;
    for (int t = tid; t < 15 * ATQ; t += 128) Q[49 * ATQ + t] = 0.f;

    for (int t = tid; t < WN * 8; t += 128) {
        int n = t >> 3, d4 = (t & 7) * 4;
        const float* base = qkv + (size_t)(widx * WN + n) * QKVDIM + head * HD + d4;
        float4 q4 = *(const float4*)(base);
        float4 k4 = *(const float4*)(base + CDIM);
        float4 v4 = *(const float4*)(base + 2 * CDIM);
        *(float4*)&Q[n * ATQ + d4] = make_float4(round_tf32(q4.x), round_tf32(q4.y),
                                                 round_tf32(q4.z), round_tf32(q4.w));
        Kt[(d4 + 0) * ATK + n] = round_tf32(k4.x);
        Kt[(d4 + 1) * ATK + n] = round_tf32(k4.y);
        Kt[(d4 + 2) * ATK + n] = round_tf32(k4.z);
        Kt[(d4 + 3) * ATK + n] = round_tf32(k4.w);
        *(float4*)&V[n * ATV + d4] = make_float4(round_tf32(v4.x), round_tf32(v4.y),
                                                 round_tf32(v4.z), round_tf32(v4.w));
    }
    __syncthreads();

    // Phase 1: S = Q @ Kt
    {
        float sacc[7][4];
#pragma unroll
        for (int ni = 0; ni < 7; ni++)
#pragma unroll
            for (int j = 0; j < 4; j++) sacc[ni][j] = 0.f;

#pragma unroll
        for (int ks = 0; ks < 4; ks++) {
            uint32_t a[4];
            const int r = wm + (lane >> 2);
            const int c = ks * 8 + (lane & 3);
            a[0] = __float_as_uint(Q[r * ATQ + c]);
            a[1] = __float_as_uint(Q[(r + 8) * ATQ + c]);
            a[2] = __float_as_uint(Q[r * ATQ + c + 4]);
            a[3] = __float_as_uint(Q[(r + 8) * ATQ + c + 4]);
#pragma unroll
            for (int ni = 0; ni < 7; ni++) {
                uint32_t b[2];
                const int cc = ni * 8 + (lane >> 2);
                const int rk = ks * 8 + (lane & 3);
                b[0] = __float_as_uint(Kt[rk * ATK + cc]);
                b[1] = __float_as_uint(Kt[(rk + 4) * ATK + cc]);
                MMA_TF32(sacc[ni], a, b);
            }
        }
        const float scale = 0.17677669529663687f;
        const int row = wm + (lane >> 2);
#pragma unroll
        for (int ni = 0; ni < 7; ni++) {
            const int col = ni * 8 + (lane & 3) * 2;
            *(float2*)&S[row * ATS + col]       = make_float2(sacc[ni][0] * scale, sacc[ni][1] * scale);
            *(float2*)&S[(row + 8) * ATS + col] = make_float2(sacc[ni][2] * scale, sacc[ni][3] * scale);
        }
    }
    __syncthreads();

    // softmax (valid rows), store P pre-rounded to tf32; zero pad cols
    for (int i = warp; i < WN; i += 4) {
        float v0 = S[i * ATS + lane];
        float v1 = (lane < 17) ? S[i * ATS + 32 + lane] : -1e30f;
        float m = fmaxf(v0, v1);
#pragma unroll
        for (int o = 16; o > 0; o >>= 1) m = fmaxf(m, __shfl_xor_sync(0xffffffffu, m, o));
        float e0 = __expf(v0 - m);
        float e1 = (lane < 17) ? __expf(v1 - m) : 0.f;
        float s = e0 + e1;
#pragma unroll
        for (int o = 16; o > 0; o >>= 1) s += __shfl_xor_sync(0xffffffffu, s, o);
        float inv = 1.f / s;
        S[i * ATS + lane] = round_tf32(e0 * inv);
        if (lane < 17)      S[i * ATS + 32 + lane] = round_tf32(e1 * inv);
        else if (lane < 24) S[i * ATS + 32 + lane] = 0.f;
    }
    __syncthreads();

    // Phase 2: O = P @ V
    {
        float oacc[4][4];
#pragma unroll
        for (int ni = 0; ni < 4; ni++)
#pragma unroll
            for (int j = 0; j < 4; j++) oacc[ni][j] = 0.f;

#pragma unroll
        for (int ks = 0; ks < 7; ks++) {
            uint32_t a[4];
            const int r = wm + (lane >> 2);
            const int c = ks * 8 + (lane & 3);
            a[0] = __float_as_uint(S[r * ATS + c]);
            a[1] = __float_as_uint(S[(r + 8) * ATS + c]);
            a[2] = __float_as_uint(S[r * ATS + c + 4]);
            a[3] = __float_as_uint(S[(r + 8) * ATS + c + 4]);
#pragma unroll
            for (int ni = 0; ni < 4; ni++) {
                uint32_t b[2];
                const int cc = ni * 8 + (lane >> 2);
                const int rk = ks * 8 + (lane & 3);
                b[0] = __float_as_uint(V[rk * ATV + cc]);
                b[1] = __float_as_uint(V[(rk + 4) * ATV + cc]);
                MMA_TF32(oacc[ni], a, b);
            }
        }
#pragma unroll
        for (int h = 0; h < 2; h++) {
            const int row = wm + (lane >> 2) + h * 8;
            if (row < WN) {
                float* orow = out + (size_t)(widx * WN + row) * CDIM + head * HD;
#pragma unroll
                for (int ni = 0; ni < 4; ni++) {
                    const int col = ni * 8 + (lane & 3) * 2;
                    *(float2*)(orow + col) = make_float2(round_tf32(oacc[ni][2 * h + 0]),
                                                         round_tf32(oacc[ni][2 * h + 1]));
                }
            }
        }
    }
}

// ---------------------------------------------------------------------------
// Launch
// ---------------------------------------------------------------------------
extern "C" void kernel_launch(void* const* d_in, const int* in_sizes, int n_in,
                              void* d_out, int out_size)
{
    const float* x      = (const float*)d_in[0];
    const float* qkv_w  = (const float*)d_in[1];
    const float* qkv_b  = (const float*)d_in[2];
    const float* proj_w = (const float*)d_in[3];
    const float* proj_b = (const float*)d_in[4];
    const float* g1     = (const float*)d_in[5];
    const float* be1    = (const float*)d_in[6];
    const float* g2     = (const float*)d_in[7];
    const float* be2    = (const float*)d_in[8];
    const float* w1     = (const float*)d_in[9];
    const float* b1     = (const float*)d_in[10];
    const float* w2     = (const float*)d_in[11];
    const float* b2     = (const float*)d_in[12];
    float* out = (float*)d_out;

    float *xn, *qkvbuf, *attnbuf, *xa, *wq, *wp, *wf1, *wf2;
    cudaGetSymbolAddress((void**)&xn,      g_xn);
    cudaGetSymbolAddress((void**)&qkvbuf,  g_qkv);
    cudaGetSymbolAddress((void**)&attnbuf, g_attn);
    cudaGetSymbolAddress((void**)&xa,      g_xa);
    cudaGetSymbolAddress((void**)&wq,      g_wq);
    cudaGetSymbolAddress((void**)&wp,      g_wp);
    cudaGetSymbolAddress((void**)&wf1,     g_w1);
    cudaGetSymbolAddress((void**)&wf2,     g_w2);

    const int lnBlocks = (TOK * 32) / 256;

    // 0) weights -> tf32, transposed to [N][K]
    wconv_kernel<<<432, 256>>>(qkv_w, wq, CDIM, QKVDIM,
                               proj_w, wp, CDIM, CDIM,
                               w1, wf1, CDIM, HIDDEN,
                               w2, wf2, HIDDEN, CDIM);

    // 1) shift+window gather + LN1 -> xn
    ln_kernel<<<lnBlocks, 256>>>(x, g1, be1, xn, 1);

    // 2) QKV GEMM
    gemm_tc<EPI_BIAS><<<dim3(QKVDIM / 64, TOK / 128), 256>>>(
        xn, wq, qkv_b, qkvbuf, nullptr, TOK, QKVDIM, CDIM);

    // 3) windowed MHA
    attn_mma_kernel<<<dim3(NWIN, NHEAD), 128>>>(qkvbuf, attnbuf);

    // 4) proj GEMM + scatter -> xa
    gemm_tc<EPI_PROJ><<<dim3(CDIM / 64, TOK / 128), 256>>>(
        attnbuf, wp, proj_b, xa, nullptr, TOK, CDIM, CDIM);

    // 5) LN2 -> xn
    ln_kernel<<<lnBlocks, 256>>>(xa, g2, be2, xn, 0);

    // 6) MLP fc1 + GELU -> qkvbuf
    gemm_tc<EPI_GELU><<<dim3(HIDDEN / 64, TOK / 128), 256>>>(
        xn, wf1, b1, qkvbuf, nullptr, TOK, HIDDEN, CDIM);

    // 7) MLP fc2 + residual -> out
    gemm_tc<EPI_RES><<<dim3(CDIM / 64, TOK / 128), 256>>>(
        qkvbuf, wf2, b2, out, xa, TOK, CDIM, HIDDEN);
}